// round 15
// baseline (speedup 1.0000x reference)
#include <cuda_runtime.h>
#include <cuda_fp16.h>
#include <cstdint>

#define NN 100000
#define NE 1600000
#define NG 512
#define FIN 20
#define HID 128
#define OUTF 64
#define NSCAN_BLK ((NN + 1023) / 1024)   // 98

// ---------------- scratch (device globals; no allocation allowed) ----------------
__device__ __align__(16) __half g_x16[(size_t)NN * 32];    // x * dinv[row], fp16, rows padded to 64B
__device__ __align__(16) __half g_h[(size_t)NN * HID];     // node features (post relu), fp16
__device__ __align__(16) __half g_xw[(size_t)NN * HID];    // gemm output * dinv[row], fp16
__device__ __align__(16) __half g_Wt[2][HID * HID];        // W2^T, W3^T in fp16 (n-major)
__device__ float g_dinv[NN];
__device__ int   g_deg[NN];                                // EDGE-only degree (self loop excluded)
__device__ int   g_rowptr[NN + 1];
__device__ int   g_cursor[NN];
__device__ int   g_col[NE];                                // CSR without self loops
__device__ int   g_part[NSCAN_BLK + 32];
__device__ int   g_gcnt[NG];
__device__ int   g_gstart[NG + 1];
__device__ int   g_is64;
__device__ int   g_barA;                                   // grid barrier: arrivals
__device__ int   g_barR;                                   // grid barrier: released phase

// monotonic-phase grid barrier (all NB blocks resident by construction)
__device__ __forceinline__ void gbar(int phase, int nb) {
    __syncthreads();
    if (threadIdx.x == 0) {
        __threadfence();
        if (atomicAdd(&g_barA, 1) == nb - 1) {
            atomicExch(&g_barA, 0);
            atomicExch(&g_barR, phase);
        } else {
            while (atomicAdd(&g_barR, 0) < phase) __nanosleep(64);
        }
        __threadfence();
    }
    __syncthreads();
}

// dtype-agnostic index load (edge_index/batch may be int32 or int64)
__device__ __forceinline__ int load_idx(const void* p, int is64, long long i) {
    if (is64) return (int)((const long long*)p)[i];
    return ((const int*)p)[i];
}

// ---------------- mma / ldmatrix wrappers ----------------
__device__ __forceinline__ void ldsm_x4(uint32_t addr, uint32_t& r0, uint32_t& r1,
                                        uint32_t& r2, uint32_t& r3) {
    asm volatile("ldmatrix.sync.aligned.m8n8.x4.shared.b16 {%0,%1,%2,%3}, [%4];"
                 : "=r"(r0), "=r"(r1), "=r"(r2), "=r"(r3) : "r"(addr));
}
__device__ __forceinline__ void ldsm_x2(uint32_t addr, uint32_t& r0, uint32_t& r1) {
    asm volatile("ldmatrix.sync.aligned.m8n8.x2.shared.b16 {%0,%1}, [%2];"
                 : "=r"(r0), "=r"(r1) : "r"(addr));
}
__device__ __forceinline__ void mma16816(float* c, uint32_t a0, uint32_t a1, uint32_t a2,
                                         uint32_t a3, uint32_t b0, uint32_t b1) {
    asm volatile(
        "mma.sync.aligned.m16n8k16.row.col.f32.f16.f16.f32 "
        "{%0,%1,%2,%3},{%4,%5,%6,%7},{%8,%9},{%0,%1,%2,%3};"
        : "+f"(c[0]), "+f"(c[1]), "+f"(c[2]), "+f"(c[3])
        : "r"(a0), "r"(a1), "r"(a2), "r"(a3), "r"(b0), "r"(b1));
}

// ---------------- hidden-layer MMA phase (Wsh loaded ONCE per block) ----------------
__device__ void mma_phase(char* su, int widx, int NB) {
    __half* Ash = (__half*)su;             // 16 KB swizzled
    __half* Wsh = (__half*)(su + 16384);   // 32 KB swizzled
    int t = threadIdx.x;
    const __half* Wt = g_Wt[widx];
    for (int i = t; i < 128 * 16; i += 256) {
        int row = i >> 4, ch = i & 15;
        uint4 v = *(const uint4*)&Wt[(size_t)row * HID + ch * 8];
        *(uint4*)((char*)Wsh + row * 256 + ((ch ^ (row & 7)) << 4)) = v;
    }
    int w = t >> 5, lane = t & 31;
    int mb = (w & 3) * 16;
    int nb8 = (w >> 2) * 8;
    uint32_t AshB = (uint32_t)__cvta_generic_to_shared(Ash);
    uint32_t WshB = (uint32_t)__cvta_generic_to_shared(Wsh);
    int sel = lane >> 3, r8 = lane & 7;
    const int ntile = (NN + 63) / 64;

    for (int tile = blockIdx.x; tile < ntile; tile += NB) {
        int bn = tile * 64;
        __syncthreads();   // previous iteration's readers done with Ash (also covers Wsh ready)
        for (int i = t; i < 64 * 16; i += 256) {
            int row = i >> 4, ch = i & 15;
            int gr = bn + row;
            uint4 v = make_uint4(0u, 0u, 0u, 0u);
            if (gr < NN) v = *(const uint4*)&g_h[(size_t)gr * HID + ch * 8];
            *(uint4*)((char*)Ash + row * 256 + ((ch ^ (row & 7)) << 4)) = v;
        }
        __syncthreads();

        float c[8][4];
        #pragma unroll
        for (int i = 0; i < 8; i++)
            #pragma unroll
            for (int j = 0; j < 4; j++) c[i][j] = 0.f;

        #pragma unroll
        for (int ks = 0; ks < 8; ks++) {
            int arow = mb + r8 + ((sel & 1) << 3);
            int ach = ks * 2 + (sel >> 1);
            uint32_t a0, a1, a2, a3;
            ldsm_x4(AshB + arow * 256 + ((ach ^ (arow & 7)) << 4), a0, a1, a2, a3);
            #pragma unroll
            for (int nt = 0; nt < 8; nt++) {
                int brow = (nb8 + nt) * 8 + r8;
                uint32_t b0, b1;
                ldsm_x2(WshB + brow * 256 + (((ks * 2 + ((lane >> 3) & 1)) ^ (brow & 7)) << 4), b0, b1);
                mma16816(c[nt], a0, a1, a2, a3, b0, b1);
            }
        }

        int r1 = bn + mb + (lane >> 2);
        int r2 = r1 + 8;
        float s1 = (r1 < NN) ? g_dinv[r1] : 0.f;
        float s2 = (r2 < NN) ? g_dinv[r2] : 0.f;
        #pragma unroll
        for (int nt = 0; nt < 8; nt++) {
            int col = (nb8 + nt) * 8 + (lane & 3) * 2;
            if (r1 < NN)
                *(__half2*)&g_xw[(size_t)r1 * HID + col] = __floats2half2_rn(c[nt][0] * s1, c[nt][1] * s1);
            if (r2 < NN)
                *(__half2*)&g_xw[(size_t)r2 * HID + col] = __floats2half2_rn(c[nt][2] * s2, c[nt][3] * s2);
        }
    }
}

// ---------------- hidden-layer aggregation phase (warp per node, 4-wide MLP) ----------------
__device__ void agg_h_phase(const float* __restrict__ bias, int NB) {
    int lane = threadIdx.x & 31;
    int gw = (blockIdx.x * 256 + threadIdx.x) >> 5;
    int nw = (NB * 256) >> 5;
    for (int wid = gw; wid < NN; wid += nw) {
        int r = g_rowptr[wid], e = g_rowptr[wid + 1];
        uint2 v0 = *(const uint2*)&g_xw[(size_t)wid * HID + lane * 4];  // self loop
        float2 f0 = __half22float2(*(__half2*)&v0.x);
        float2 f1 = __half22float2(*(__half2*)&v0.y);
        float4 acc = make_float4(f0.x, f0.y, f1.x, f1.y);
        int j = r;
        for (; j + 4 <= e; j += 4) {
            int s0 = g_col[j], s1 = g_col[j + 1], s2 = g_col[j + 2], s3 = g_col[j + 3];
            uint2 w0 = *(const uint2*)&g_xw[(size_t)s0 * HID + lane * 4];
            uint2 w1 = *(const uint2*)&g_xw[(size_t)s1 * HID + lane * 4];
            uint2 w2 = *(const uint2*)&g_xw[(size_t)s2 * HID + lane * 4];
            uint2 w3 = *(const uint2*)&g_xw[(size_t)s3 * HID + lane * 4];
            float2 a0 = __half22float2(*(__half2*)&w0.x), a1 = __half22float2(*(__half2*)&w0.y);
            float2 b0 = __half22float2(*(__half2*)&w1.x), b1 = __half22float2(*(__half2*)&w1.y);
            float2 c0 = __half22float2(*(__half2*)&w2.x), c1 = __half22float2(*(__half2*)&w2.y);
            float2 d0 = __half22float2(*(__half2*)&w3.x), d1 = __half22float2(*(__half2*)&w3.y);
            acc.x += (a0.x + b0.x) + (c0.x + d0.x);
            acc.y += (a0.y + b0.y) + (c0.y + d0.y);
            acc.z += (a1.x + b1.x) + (c1.x + d1.x);
            acc.w += (a1.y + b1.y) + (c1.y + d1.y);
        }
        for (; j < e; j++) {
            int s = g_col[j];
            uint2 v = *(const uint2*)&g_xw[(size_t)s * HID + lane * 4];
            float2 a0 = __half22float2(*(__half2*)&v.x);
            float2 a1 = __half22float2(*(__half2*)&v.y);
            acc.x += a0.x; acc.y += a0.y; acc.z += a1.x; acc.w += a1.y;
        }
        float dn = g_dinv[wid];
        float4 b = *(const float4*)&bias[lane * 4];
        float ox = fmaxf(acc.x * dn + b.x, 0.f), oy = fmaxf(acc.y * dn + b.y, 0.f);
        float oz = fmaxf(acc.z * dn + b.z, 0.f), ow = fmaxf(acc.w * dn + b.w, 0.f);
        __half2* p = (__half2*)&g_h[(size_t)wid * HID + lane * 4];
        p[0] = __floats2half2_rn(ox, oy);
        p[1] = __floats2half2_rn(oz, ow);
    }
}

// ---------------- the single persistent kernel ----------------
extern "C" __global__ void __launch_bounds__(256, 2)
k_mono(const float* __restrict__ x, const void* __restrict__ ei,
       const void* __restrict__ batch,
       const float* __restrict__ W1, const float* __restrict__ b1,
       const float* __restrict__ W2, const float* __restrict__ b2,
       const float* __restrict__ W3, const float* __restrict__ b3,
       const float* __restrict__ Wout, const float* __restrict__ bout,
       float* __restrict__ out, int NB) {
    __shared__ __align__(16) char su[49152];   // phase-union scratch (48 KB)
    int t = threadIdx.x, lane = t & 31, w = t >> 5;
    int gid = blockIdx.x * 256 + t;
    int gsz = NB * 256;

    // ---- P0: zero deg/gcnt, dtype detect, weight convert ----
    for (int i = gid; i < NN; i += gsz) g_deg[i] = 0;
    if (gid < NG) g_gcnt[gid] = 0;
    if (gid == 0) {
        const int* e32 = (const int*)ei;
        int z = 0;
        #pragma unroll
        for (int q = 1; q < 64; q += 2) z |= e32[q];
        g_is64 = (z == 0) ? 1 : 0;
    }
    for (int id = gid; id < 2 * HID * HID; id += gsz) {
        int ww = id >> 14, e = id & 16383;
        int n = e >> 7, k = e & 127;
        const float* W = ww ? W3 : W2;
        g_Wt[ww][n * HID + k] = __float2half_rn(W[k * HID + n]);
    }
    gbar(1, NB);

    // ---- P1: degree + graph-count atomics ----
    {
        int is64 = g_is64;
        for (int i = gid; i < NE; i += gsz)
            atomicAdd(&g_deg[load_idx(ei, is64, (long long)NE + i)], 1);
        for (int i = gid; i < NN; i += gsz)
            atomicAdd(&g_gcnt[load_idx(batch, is64, i)], 1);
    }
    gbar(2, NB);

    // ---- P2: per-1024-chunk partial sums ----
    {
        int* ws = (int*)su;
        for (int c = blockIdx.x; c < NSCAN_BLK; c += NB) {
            int base = c * 1024 + t * 4;
            int s = 0;
            #pragma unroll
            for (int i = 0; i < 4; i++) {
                int idx = base + i;
                if (idx < NN) s += g_deg[idx];
            }
            #pragma unroll
            for (int o = 16; o; o >>= 1) s += __shfl_down_sync(0xffffffffu, s, o);
            if (lane == 0) ws[w] = s;
            __syncthreads();
            if (t == 0) {
                int tot = 0;
                #pragma unroll
                for (int i = 0; i < 8; i++) tot += ws[i];
                g_part[c] = tot;
            }
            __syncthreads();
        }
    }
    gbar(3, NB);

    // ---- P3: scan partials (block 0) + scan graph counts (block 1) ----
    if (blockIdx.x == 0) {
        int* wsum = (int*)su;
        int v = (t < NSCAN_BLK) ? g_part[t] : 0;
        int xv = v;
        #pragma unroll
        for (int o = 1; o < 32; o <<= 1) {
            int y = __shfl_up_sync(0xffffffffu, xv, o);
            if (lane >= o) xv += y;
        }
        if (lane == 31) wsum[w] = xv;
        __syncthreads();
        if (t == 0) {
            int run = 0;
            #pragma unroll
            for (int i = 0; i < 8; i++) { int tmp = wsum[i]; wsum[i] = run; run += tmp; }
        }
        __syncthreads();
        int incl = xv + wsum[w];
        if (t < NSCAN_BLK) g_part[t] = incl - v;
        if (t == 0) g_rowptr[NN] = NE;
    } else if (blockIdx.x == 1) {
        int* wsum = (int*)su;
        int v0 = g_gcnt[2 * t], v1 = g_gcnt[2 * t + 1];
        int p = v0 + v1;
        int xp = p;
        #pragma unroll
        for (int o = 1; o < 32; o <<= 1) {
            int y = __shfl_up_sync(0xffffffffu, xp, o);
            if (lane >= o) xp += y;
        }
        if (lane == 31) wsum[w] = xp;
        __syncthreads();
        if (t == 0) {
            int run = 0;
            #pragma unroll
            for (int i = 0; i < 8; i++) { int tmp = wsum[i]; wsum[i] = run; run += tmp; }
        }
        __syncthreads();
        int incl = xp + wsum[w];
        int excl = incl - p;
        g_gstart[2 * t] = excl;
        g_gstart[2 * t + 1] = excl + v0;
        if (t == 255) g_gstart[NG] = incl;
    }
    gbar(4, NB);

    // ---- P4: final scan + dinv + x->fp16 prescale ----
    {
        int* wsum = (int*)su;
        for (int c = blockIdx.x; c < NSCAN_BLK; c += NB) {
            int base = c * 1024 + t * 4;
            int v[4];
            int tsum = 0;
            #pragma unroll
            for (int i = 0; i < 4; i++) {
                v[i] = (base + i < NN) ? g_deg[base + i] : 0;
                tsum += v[i];
            }
            int xs = tsum;
            #pragma unroll
            for (int o = 1; o < 32; o <<= 1) {
                int y = __shfl_up_sync(0xffffffffu, xs, o);
                if (lane >= o) xs += y;
            }
            if (lane == 31) wsum[w] = xs;
            __syncthreads();
            if (t == 0) {
                int run = 0;
                #pragma unroll
                for (int i = 0; i < 8; i++) { int tmp = wsum[i]; wsum[i] = run; run += tmp; }
            }
            __syncthreads();
            int run = xs - tsum + wsum[w] + g_part[c];
            #pragma unroll
            for (int i = 0; i < 4; i++) {
                int row = base + i;
                if (row < NN) {
                    g_rowptr[row] = run;
                    g_cursor[row] = run;
                    float dn = rsqrtf((float)(v[i] + 1));   // +1 self loop
                    g_dinv[row] = dn;
                    run += v[i];
                    const float4* xr = (const float4*)(x + (size_t)row * FIN);
                    float f[20];
                    #pragma unroll
                    for (int q = 0; q < 5; q++) {
                        float4 v4 = xr[q];
                        f[q * 4] = v4.x; f[q * 4 + 1] = v4.y; f[q * 4 + 2] = v4.z; f[q * 4 + 3] = v4.w;
                    }
                    __align__(16) __half2 h[16];
                    #pragma unroll
                    for (int cc = 0; cc < 10; cc++) h[cc] = __floats2half2_rn(f[2 * cc] * dn, f[2 * cc + 1] * dn);
                    #pragma unroll
                    for (int cc = 10; cc < 16; cc++) h[cc] = __floats2half2_rn(0.f, 0.f);
                    uint4* dst = (uint4*)&g_x16[(size_t)row * 32];
                    const uint4* src = (const uint4*)h;
                    dst[0] = src[0]; dst[1] = src[1]; dst[2] = src[2]; dst[3] = src[3];
                }
            }
            __syncthreads();
        }
    }
    gbar(5, NB);

    // ---- P5: scatter edges into CSR ----
    {
        int is64 = g_is64;
        for (int e = gid; e < NE; e += gsz) {
            int s = load_idx(ei, is64, e);
            int d = load_idx(ei, is64, (long long)NE + e);
            int pos = atomicAdd(&g_cursor[d], 1);
            g_col[pos] = s;
        }
    }
    gbar(6, NB);

    // ---- P6: layer 1 — aggregate prescaled x + 20x128 GEMM + bias + relu ----
    {
        float* Wsh1 = (float*)su;              // 10 KB
        float* xsh = (float*)(su + 10240);     // 5 KB
        for (int i = t; i < FIN * HID; i += 256) Wsh1[i] = W1[i];
        __syncthreads();
        const int ntile = (NN + 63) / 64;
        for (int tile = blockIdx.x; tile < ntile; tile += NB) {
            int bn = tile * 64;
            // warp-private agg: warp w handles nodes bn+w*8 .. +7 into its own xsh rows
            for (int ni = 0; ni < 8; ni++) {
                int node = bn + w * 8 + ni;
                float2 acc = make_float2(0.f, 0.f);
                if (node < NN) {
                    int r = g_rowptr[node], e = g_rowptr[node + 1];
                    if (lane < 16)
                        acc = __half22float2(*(const __half2*)&g_x16[(size_t)node * 32 + lane * 2]);
                    int j = r;
                    for (; j + 4 <= e; j += 4) {
                        int s0 = g_col[j], s1 = g_col[j + 1], s2 = g_col[j + 2], s3 = g_col[j + 3];
                        if (lane < 16) {
                            float2 f0 = __half22float2(*(const __half2*)&g_x16[(size_t)s0 * 32 + lane * 2]);
                            float2 f1 = __half22float2(*(const __half2*)&g_x16[(size_t)s1 * 32 + lane * 2]);
                            float2 f2 = __half22float2(*(const __half2*)&g_x16[(size_t)s2 * 32 + lane * 2]);
                            float2 f3 = __half22float2(*(const __half2*)&g_x16[(size_t)s3 * 32 + lane * 2]);
                            acc.x += (f0.x + f1.x) + (f2.x + f3.x);
                            acc.y += (f0.y + f1.y) + (f2.y + f3.y);
                        }
                    }
                    for (; j < e; j++) {
                        int s = g_col[j];
                        if (lane < 16) {
                            float2 f = __half22float2(*(const __half2*)&g_x16[(size_t)s * 32 + lane * 2]);
                            acc.x += f.x; acc.y += f.y;
                        }
                    }
                    if (lane < 10) {
                        float dn = g_dinv[node];
                        xsh[(w * 8 + ni) * FIN + lane * 2]     = acc.x * dn;
                        xsh[(w * 8 + ni) * FIN + lane * 2 + 1] = acc.y * dn;
                    }
                } else if (lane < 10) {
                    xsh[(w * 8 + ni) * FIN + lane * 2]     = 0.f;
                    xsh[(w * 8 + ni) * FIN + lane * 2 + 1] = 0.f;
                }
            }
            __syncwarp();
            // GEMM: warp w reads only its own xsh rows
            int c4 = lane * 4;
            float4 acc[8];
            #pragma unroll
            for (int i = 0; i < 8; i++) acc[i] = make_float4(0.f, 0.f, 0.f, 0.f);
            for (int k = 0; k < FIN; k++) {
                float4 wv = *(const float4*)&Wsh1[k * HID + c4];
                #pragma unroll
                for (int i = 0; i < 8; i++) {
                    float xv = xsh[(w * 8 + i) * FIN + k];
                    acc[i].x += wv.x * xv; acc[i].y += wv.y * xv;
                    acc[i].z += wv.z * xv; acc[i].w += wv.w * xv;
                }
            }
            float4 bb = *(const float4*)&b1[c4];
            #pragma unroll
            for (int i = 0; i < 8; i++) {
                int n = bn + w * 8 + i;
                if (n < NN) {
                    float ox = fmaxf(acc[i].x + bb.x, 0.f), oy = fmaxf(acc[i].y + bb.y, 0.f);
                    float oz = fmaxf(acc[i].z + bb.z, 0.f), ow = fmaxf(acc[i].w + bb.w, 0.f);
                    __half2* p = (__half2*)&g_h[(size_t)n * HID + c4];
                    p[0] = __floats2half2_rn(ox, oy);
                    p[1] = __floats2half2_rn(oz, ow);
                }
            }
            __syncwarp();
        }
    }
    gbar(7, NB);

    // ---- P7: layer-2 GEMM (tensor cores) ----
    mma_phase(su, 0, NB);
    gbar(8, NB);

    // ---- P8: layer-2 aggregation ----
    agg_h_phase(b2, NB);
    gbar(9, NB);

    // ---- P9: layer-3 GEMM ----
    mma_phase(su, 1, NB);
    gbar(10, NB);

    // ---- P10: layer-3 aggregation ----
    agg_h_phase(b3, NB);
    gbar(11, NB);

    // ---- P11: mean-pool + output head ----
    {
        float* pooled = (float*)su;
        for (int gg = blockIdx.x; gg < NG; gg += NB) {
            int st = g_gstart[gg], en = g_gstart[gg + 1];
            if (t < HID) {
                float acc = 0.f;
                for (int n = st; n < en; n++) acc += __half2float(g_h[(size_t)n * HID + t]);
                float cnt = (float)(en - st);
                if (cnt < 1.f) cnt = 1.f;
                pooled[t] = acc / cnt;
            }
            __syncthreads();
            if (t < OUTF) {
                float o = bout[t];
                #pragma unroll 8
                for (int k = 0; k < HID; k++) o += pooled[k] * Wout[k * OUTF + t];
                out[(size_t)gg * OUTF + t] = o;
            }
            __syncthreads();
        }
    }

    // ---- exit: reset barrier state for the next (deterministic) replay ----
    __syncthreads();
    if (t == 0) {
        if (atomicAdd(&g_barA, 1) == NB - 1) {
            atomicExch(&g_barA, 0);
            atomicExch(&g_barR, 0);
        }
    }
}

// ---------------- launcher: single persistent launch ----------------
extern "C" void kernel_launch(void* const* d_in, const int* in_sizes, int n_in,
                              void* d_out, int out_size) {
    const float* x     = (const float*)d_in[0];
    const void*  ei    = d_in[1];
    const void*  batch = d_in[2];
    const float* W1 = (const float*)d_in[3];  const float* b1 = (const float*)d_in[4];
    const float* W2 = (const float*)d_in[5];  const float* b2 = (const float*)d_in[6];
    const float* W3 = (const float*)d_in[7];  const float* b3 = (const float*)d_in[8];
    const float* Wout = (const float*)d_in[9]; const float* bout = (const float*)d_in[10];
    float* out = (float*)d_out;

    int dev = 0;
    cudaGetDevice(&dev);
    int sms = 0;
    cudaDeviceGetAttribute(&sms, cudaDevAttrMultiProcessorCount, dev);
    int per = 0;
    cudaOccupancyMaxActiveBlocksPerMultiprocessor(&per, k_mono, 256, 0);
    if (per < 1) per = 1;
    if (sms < 1) sms = 1;
    int NB = sms * per;   // guaranteed co-resident -> grid barrier is live

    k_mono<<<NB, 256>>>(x, ei, batch, W1, b1, W2, b2, W3, b3, Wout, bout, out, NB);
}

// round 16
// speedup vs baseline: 1.0377x; 1.0377x over previous
#include <cuda_runtime.h>
#include <cuda_fp16.h>
#include <cstdint>

#define NN 100000
#define NE 1600000
#define NG 512
#define FIN 20
#define HID 128
#define OUTF 64
#define NSCAN_BLK ((NN + 1023) / 1024)   // 98

// ---------------- scratch (device globals; no allocation allowed) ----------------
__device__ __align__(16) __half g_x16[(size_t)NN * 32];    // x * dinv[row], fp16, rows padded to 64B
__device__ __align__(16) __half g_h[(size_t)NN * HID];     // node features (post relu), fp16
__device__ __align__(16) __half g_xw[(size_t)NN * HID];    // gemm output * dinv[row], fp16
__device__ __align__(16) __half g_Wt[2][HID * HID];        // W2^T, W3^T in fp16 (n-major)
__device__ float g_dinv[NN];
__device__ int   g_deg[NN];                                // EDGE-only degree (self loop excluded)
__device__ int   g_rowptr[NN + 1];
__device__ int   g_cursor[NN];
__device__ int   g_col[NE];                                // CSR without self loops
__device__ int   g_part[NSCAN_BLK + 32];
__device__ int   g_gcnt[NG];
__device__ int   g_gstart[NG + 1];
__device__ int   g_is64;
__device__ int   g_barA;                                   // grid barrier: arrivals
__device__ int   g_barR;                                   // grid barrier: released phase

// monotonic-phase grid barrier (all NB blocks resident by construction)
__device__ __forceinline__ void gbar(int phase, int nb) {
    __syncthreads();
    if (threadIdx.x == 0) {
        __threadfence();
        if (atomicAdd(&g_barA, 1) == nb - 1) {
            atomicExch(&g_barA, 0);
            atomicExch(&g_barR, phase);
        } else {
            while (atomicAdd(&g_barR, 0) < phase) __nanosleep(64);
        }
        __threadfence();
    }
    __syncthreads();
}

// dtype-agnostic index load (edge_index/batch may be int32 or int64)
__device__ __forceinline__ int load_idx(const void* p, int is64, long long i) {
    if (is64) return (int)((const long long*)p)[i];
    return ((const int*)p)[i];
}

// ---------------- mma / ldmatrix wrappers ----------------
__device__ __forceinline__ void ldsm_x4(uint32_t addr, uint32_t& r0, uint32_t& r1,
                                        uint32_t& r2, uint32_t& r3) {
    asm volatile("ldmatrix.sync.aligned.m8n8.x4.shared.b16 {%0,%1,%2,%3}, [%4];"
                 : "=r"(r0), "=r"(r1), "=r"(r2), "=r"(r3) : "r"(addr));
}
__device__ __forceinline__ void ldsm_x2(uint32_t addr, uint32_t& r0, uint32_t& r1) {
    asm volatile("ldmatrix.sync.aligned.m8n8.x2.shared.b16 {%0,%1}, [%2];"
                 : "=r"(r0), "=r"(r1) : "r"(addr));
}
__device__ __forceinline__ void mma16816(float* c, uint32_t a0, uint32_t a1, uint32_t a2,
                                         uint32_t a3, uint32_t b0, uint32_t b1) {
    asm volatile(
        "mma.sync.aligned.m16n8k16.row.col.f32.f16.f16.f32 "
        "{%0,%1,%2,%3},{%4,%5,%6,%7},{%8,%9},{%0,%1,%2,%3};"
        : "+f"(c[0]), "+f"(c[1]), "+f"(c[2]), "+f"(c[3])
        : "r"(a0), "r"(a1), "r"(a2), "r"(a3), "r"(b0), "r"(b1));
}

// ================= K1: persistent setup kernel (LOW registers -> high occupancy) =================
extern "C" __global__ void k_setup(const float* __restrict__ x, const void* __restrict__ ei,
                                   const void* __restrict__ batch,
                                   const float* __restrict__ W2, const float* __restrict__ W3,
                                   int NB) {
    __shared__ int sbuf[8];
    int t = threadIdx.x, lane = t & 31, w = t >> 5;
    int gid = blockIdx.x * 256 + t;
    int gsz = NB * 256;

    // ---- P0: zero deg/gcnt, dtype detect, weight convert ----
    for (int i = gid; i < NN; i += gsz) g_deg[i] = 0;
    if (gid < NG) g_gcnt[gid] = 0;
    if (gid == 0) {
        const int* e32 = (const int*)ei;
        int z = 0;
        #pragma unroll
        for (int q = 1; q < 64; q += 2) z |= e32[q];
        g_is64 = (z == 0) ? 1 : 0;
    }
    for (int id = gid; id < 2 * HID * HID; id += gsz) {
        int ww = id >> 14, e = id & 16383;
        int n = e >> 7, k = e & 127;
        const float* W = ww ? W3 : W2;
        g_Wt[ww][n * HID + k] = __float2half_rn(W[k * HID + n]);
    }
    gbar(1, NB);

    // ---- P1: degree + graph-count atomics ----
    {
        int is64 = g_is64;
        for (int i = gid; i < NE; i += gsz)
            atomicAdd(&g_deg[load_idx(ei, is64, (long long)NE + i)], 1);
        for (int i = gid; i < NN; i += gsz)
            atomicAdd(&g_gcnt[load_idx(batch, is64, i)], 1);
    }
    gbar(2, NB);

    // ---- P2: per-1024-chunk partial sums ----
    for (int c = blockIdx.x; c < NSCAN_BLK; c += NB) {
        int base = c * 1024 + t * 4;
        int s = 0;
        #pragma unroll
        for (int i = 0; i < 4; i++) {
            int idx = base + i;
            if (idx < NN) s += g_deg[idx];
        }
        #pragma unroll
        for (int o = 16; o; o >>= 1) s += __shfl_down_sync(0xffffffffu, s, o);
        if (lane == 0) sbuf[w] = s;
        __syncthreads();
        if (t == 0) {
            int tot = 0;
            #pragma unroll
            for (int i = 0; i < 8; i++) tot += sbuf[i];
            g_part[c] = tot;
        }
        __syncthreads();
    }
    gbar(3, NB);

    // ---- P3: scan partials (block 0) + scan graph counts (block 1) ----
    if (blockIdx.x == 0) {
        int v = (t < NSCAN_BLK) ? g_part[t] : 0;
        int xv = v;
        #pragma unroll
        for (int o = 1; o < 32; o <<= 1) {
            int y = __shfl_up_sync(0xffffffffu, xv, o);
            if (lane >= o) xv += y;
        }
        if (lane == 31) sbuf[w] = xv;
        __syncthreads();
        if (t == 0) {
            int run = 0;
            #pragma unroll
            for (int i = 0; i < 8; i++) { int tmp = sbuf[i]; sbuf[i] = run; run += tmp; }
        }
        __syncthreads();
        int incl = xv + sbuf[w];
        if (t < NSCAN_BLK) g_part[t] = incl - v;
        if (t == 0) g_rowptr[NN] = NE;
    } else if (blockIdx.x == 1) {
        int v0 = g_gcnt[2 * t], v1 = g_gcnt[2 * t + 1];
        int p = v0 + v1;
        int xp = p;
        #pragma unroll
        for (int o = 1; o < 32; o <<= 1) {
            int y = __shfl_up_sync(0xffffffffu, xp, o);
            if (lane >= o) xp += y;
        }
        if (lane == 31) sbuf[w] = xp;
        __syncthreads();
        if (t == 0) {
            int run = 0;
            #pragma unroll
            for (int i = 0; i < 8; i++) { int tmp = sbuf[i]; sbuf[i] = run; run += tmp; }
        }
        __syncthreads();
        int incl = xp + sbuf[w];
        int excl = incl - p;
        g_gstart[2 * t] = excl;
        g_gstart[2 * t + 1] = excl + v0;
        if (t == 255) g_gstart[NG] = incl;
    }
    gbar(4, NB);

    // ---- P4: final scan + dinv + x->fp16 prescale ----
    for (int c = blockIdx.x; c < NSCAN_BLK; c += NB) {
        int base = c * 1024 + t * 4;
        int v[4];
        int tsum = 0;
        #pragma unroll
        for (int i = 0; i < 4; i++) {
            v[i] = (base + i < NN) ? g_deg[base + i] : 0;
            tsum += v[i];
        }
        int xs = tsum;
        #pragma unroll
        for (int o = 1; o < 32; o <<= 1) {
            int y = __shfl_up_sync(0xffffffffu, xs, o);
            if (lane >= o) xs += y;
        }
        if (lane == 31) sbuf[w] = xs;
        __syncthreads();
        if (t == 0) {
            int run = 0;
            #pragma unroll
            for (int i = 0; i < 8; i++) { int tmp = sbuf[i]; sbuf[i] = run; run += tmp; }
        }
        __syncthreads();
        int run = xs - tsum + sbuf[w] + g_part[c];
        #pragma unroll
        for (int i = 0; i < 4; i++) {
            int row = base + i;
            if (row < NN) {
                g_rowptr[row] = run;
                g_cursor[row] = run;
                float dn = rsqrtf((float)(v[i] + 1));   // +1 self loop
                g_dinv[row] = dn;
                run += v[i];
                const float4* xr = (const float4*)(x + (size_t)row * FIN);
                __align__(16) __half2 h[16];
                #pragma unroll
                for (int q = 0; q < 5; q++) {
                    float4 v4 = xr[q];
                    h[q * 2]     = __floats2half2_rn(v4.x * dn, v4.y * dn);
                    h[q * 2 + 1] = __floats2half2_rn(v4.z * dn, v4.w * dn);
                }
                #pragma unroll
                for (int cc = 10; cc < 16; cc++) h[cc] = __floats2half2_rn(0.f, 0.f);
                uint4* dst = (uint4*)&g_x16[(size_t)row * 32];
                const uint4* src = (const uint4*)h;
                dst[0] = src[0]; dst[1] = src[1]; dst[2] = src[2]; dst[3] = src[3];
            }
        }
        __syncthreads();
    }
    gbar(5, NB);

    // ---- P5: scatter edges into CSR ----
    {
        int is64 = g_is64;
        for (int e = gid; e < NE; e += gsz) {
            int s = load_idx(ei, is64, e);
            int d = load_idx(ei, is64, (long long)NE + e);
            int pos = atomicAdd(&g_cursor[d], 1);
            g_col[pos] = s;
        }
    }

    // ---- exit: reset barrier state for the next (deterministic) replay ----
    __syncthreads();
    if (t == 0) {
        if (atomicAdd(&g_barA, 1) == NB - 1) {
            atomicExch(&g_barA, 0);
            atomicExch(&g_barR, 0);
        }
    }
}

// ================= K2: fused layer 1 (aggregate prescaled x + GEMM + bias + relu) =================
__global__ void k_aggx_gemm1(const float* __restrict__ W1, const float* __restrict__ b1) {
    __shared__ __align__(16) float Wsh[FIN * HID];  // 10 KB
    __shared__ float xsh[64 * FIN];                 // 5 KB
    int t = threadIdx.x;
    int bn = blockIdx.x * 64;
    for (int i = t; i < FIN * HID; i += 256) Wsh[i] = W1[i];

    int w = t >> 5, lane = t & 31;
    for (int ni = 0; ni < 8; ni++) {
        int node = bn + w * 8 + ni;
        float2 acc = make_float2(0.f, 0.f);
        if (node < NN) {
            int r = g_rowptr[node], e = g_rowptr[node + 1];
            if (lane < 16)
                acc = __half22float2(*(const __half2*)&g_x16[(size_t)node * 32 + lane * 2]);
            int j = r;
            for (; j + 4 <= e; j += 4) {
                int s0 = g_col[j], s1 = g_col[j + 1], s2 = g_col[j + 2], s3 = g_col[j + 3];
                if (lane < 16) {
                    float2 f0 = __half22float2(*(const __half2*)&g_x16[(size_t)s0 * 32 + lane * 2]);
                    float2 f1 = __half22float2(*(const __half2*)&g_x16[(size_t)s1 * 32 + lane * 2]);
                    float2 f2 = __half22float2(*(const __half2*)&g_x16[(size_t)s2 * 32 + lane * 2]);
                    float2 f3 = __half22float2(*(const __half2*)&g_x16[(size_t)s3 * 32 + lane * 2]);
                    acc.x += (f0.x + f1.x) + (f2.x + f3.x);
                    acc.y += (f0.y + f1.y) + (f2.y + f3.y);
                }
            }
            for (; j < e; j++) {
                int s = g_col[j];
                if (lane < 16) {
                    float2 f = __half22float2(*(const __half2*)&g_x16[(size_t)s * 32 + lane * 2]);
                    acc.x += f.x; acc.y += f.y;
                }
            }
            if (lane < 10) {
                float dn = g_dinv[node];
                xsh[(w * 8 + ni) * FIN + lane * 2]     = acc.x * dn;
                xsh[(w * 8 + ni) * FIN + lane * 2 + 1] = acc.y * dn;
            }
        } else if (lane < 10) {
            xsh[(w * 8 + ni) * FIN + lane * 2]     = 0.f;
            xsh[(w * 8 + ni) * FIN + lane * 2 + 1] = 0.f;
        }
    }
    __syncthreads();

    int c4 = lane * 4;
    float4 acc[8];
    #pragma unroll
    for (int i = 0; i < 8; i++) acc[i] = make_float4(0.f, 0.f, 0.f, 0.f);
    for (int k = 0; k < FIN; k++) {
        float4 wv = *(const float4*)&Wsh[k * HID + c4];
        #pragma unroll
        for (int i = 0; i < 8; i++) {
            float xv = xsh[(w * 8 + i) * FIN + k];
            acc[i].x += wv.x * xv; acc[i].y += wv.y * xv;
            acc[i].z += wv.z * xv; acc[i].w += wv.w * xv;
        }
    }
    float4 bb = *(const float4*)&b1[c4];
    #pragma unroll
    for (int i = 0; i < 8; i++) {
        int n = bn + w * 8 + i;
        if (n < NN) {
            float ox = fmaxf(acc[i].x + bb.x, 0.f), oy = fmaxf(acc[i].y + bb.y, 0.f);
            float oz = fmaxf(acc[i].z + bb.z, 0.f), ow = fmaxf(acc[i].w + bb.w, 0.f);
            __half2* p = (__half2*)&g_h[(size_t)n * HID + c4];
            p[0] = __floats2half2_rn(ox, oy);
            p[1] = __floats2half2_rn(oz, ow);
        }
    }
}

// ================= K3/K5: hidden GEMM (tensor cores) =================
__global__ __launch_bounds__(256, 2) void k_gemm_mma(int widx) {
    __shared__ __align__(16) __half Ash[64 * HID];    // 16 KB, swizzled
    __shared__ __align__(16) __half Wsh[HID * HID];   // 32 KB, swizzled
    int t = threadIdx.x;
    int bn = blockIdx.x * 64;

    for (int i = t; i < 64 * 16; i += 256) {
        int row = i >> 4, ch = i & 15;
        int gr = bn + row;
        uint4 v = make_uint4(0u, 0u, 0u, 0u);
        if (gr < NN) v = *(const uint4*)&g_h[(size_t)gr * HID + ch * 8];
        *(uint4*)((char*)Ash + row * 256 + ((ch ^ (row & 7)) << 4)) = v;
    }
    const __half* Wt = g_Wt[widx];
    for (int i = t; i < 128 * 16; i += 256) {
        int row = i >> 4, ch = i & 15;
        uint4 v = *(const uint4*)&Wt[(size_t)row * HID + ch * 8];
        *(uint4*)((char*)Wsh + row * 256 + ((ch ^ (row & 7)) << 4)) = v;
    }
    __syncthreads();

    int w = t >> 5, lane = t & 31;
    int mb = (w & 3) * 16;
    int nb = (w >> 2) * 8;
    uint32_t AshB = (uint32_t)__cvta_generic_to_shared(Ash);
    uint32_t WshB = (uint32_t)__cvta_generic_to_shared(Wsh);

    float c[8][4];
    #pragma unroll
    for (int i = 0; i < 8; i++)
        #pragma unroll
        for (int j = 0; j < 4; j++) c[i][j] = 0.f;

    int sel = lane >> 3, r8 = lane & 7;
    #pragma unroll
    for (int ks = 0; ks < 8; ks++) {
        int arow = mb + r8 + ((sel & 1) << 3);
        int ach = ks * 2 + (sel >> 1);
        uint32_t a0, a1, a2, a3;
        ldsm_x4(AshB + arow * 256 + ((ach ^ (arow & 7)) << 4), a0, a1, a2, a3);
        int bch = ks * 2 + ((lane >> 3) & 1);
        #pragma unroll
        for (int nt = 0; nt < 8; nt++) {
            int brow = (nb + nt) * 8 + r8;
            uint32_t b0, b1;
            ldsm_x2(WshB + brow * 256 + ((bch ^ (brow & 7)) << 4), b0, b1);
            mma16816(c[nt], a0, a1, a2, a3, b0, b1);
        }
    }

    int r1 = bn + mb + (lane >> 2);
    int r2 = r1 + 8;
    float s1 = (r1 < NN) ? g_dinv[r1] : 0.f;
    float s2 = (r2 < NN) ? g_dinv[r2] : 0.f;
    #pragma unroll
    for (int nt = 0; nt < 8; nt++) {
        int col = (nb + nt) * 8 + (lane & 3) * 2;
        if (r1 < NN)
            *(__half2*)&g_xw[(size_t)r1 * HID + col] = __floats2half2_rn(c[nt][0] * s1, c[nt][1] * s1);
        if (r2 < NN)
            *(__half2*)&g_xw[(size_t)r2 * HID + col] = __floats2half2_rn(c[nt][2] * s2, c[nt][3] * s2);
    }
}

// ================= K4/K6: hidden-layer aggregation (warp per node, 4-wide MLP) =================
__global__ void k_agg_h(const float* __restrict__ bias) {
    int wid = (blockIdx.x * blockDim.x + threadIdx.x) >> 5;
    int lane = threadIdx.x & 31;
    if (wid >= NN) return;
    int r = g_rowptr[wid], e = g_rowptr[wid + 1];
    uint2 v0 = *(const uint2*)&g_xw[(size_t)wid * HID + lane * 4];  // self loop
    float2 f0 = __half22float2(*(__half2*)&v0.x);
    float2 f1 = __half22float2(*(__half2*)&v0.y);
    float4 acc = make_float4(f0.x, f0.y, f1.x, f1.y);
    int j = r;
    for (; j + 4 <= e; j += 4) {
        int s0 = g_col[j], s1 = g_col[j + 1], s2 = g_col[j + 2], s3 = g_col[j + 3];
        uint2 w0 = *(const uint2*)&g_xw[(size_t)s0 * HID + lane * 4];
        uint2 w1 = *(const uint2*)&g_xw[(size_t)s1 * HID + lane * 4];
        uint2 w2 = *(const uint2*)&g_xw[(size_t)s2 * HID + lane * 4];
        uint2 w3 = *(const uint2*)&g_xw[(size_t)s3 * HID + lane * 4];
        float2 a0 = __half22float2(*(__half2*)&w0.x), a1 = __half22float2(*(__half2*)&w0.y);
        float2 b0 = __half22float2(*(__half2*)&w1.x), b1 = __half22float2(*(__half2*)&w1.y);
        float2 c0 = __half22float2(*(__half2*)&w2.x), c1 = __half22float2(*(__half2*)&w2.y);
        float2 d0 = __half22float2(*(__half2*)&w3.x), d1 = __half22float2(*(__half2*)&w3.y);
        acc.x += (a0.x + b0.x) + (c0.x + d0.x);
        acc.y += (a0.y + b0.y) + (c0.y + d0.y);
        acc.z += (a1.x + b1.x) + (c1.x + d1.x);
        acc.w += (a1.y + b1.y) + (c1.y + d1.y);
    }
    for (; j < e; j++) {
        int s = g_col[j];
        uint2 v = *(const uint2*)&g_xw[(size_t)s * HID + lane * 4];
        float2 a0 = __half22float2(*(__half2*)&v.x);
        float2 a1 = __half22float2(*(__half2*)&v.y);
        acc.x += a0.x; acc.y += a0.y; acc.z += a1.x; acc.w += a1.y;
    }
    float dn = g_dinv[wid];
    float4 b = *(const float4*)&bias[lane * 4];
    float ox = fmaxf(acc.x * dn + b.x, 0.f), oy = fmaxf(acc.y * dn + b.y, 0.f);
    float oz = fmaxf(acc.z * dn + b.z, 0.f), ow = fmaxf(acc.w * dn + b.w, 0.f);
    __half2* p = (__half2*)&g_h[(size_t)wid * HID + lane * 4];
    p[0] = __floats2half2_rn(ox, oy);
    p[1] = __floats2half2_rn(oz, ow);
}

// ================= K7: mean-pool + output head =================
__global__ void k_pool(const float* __restrict__ Wout, const float* __restrict__ bout,
                       float* __restrict__ out) {
    int gg = blockIdx.x;
    int t = threadIdx.x;  // 128
    int st = g_gstart[gg], en = g_gstart[gg + 1];
    float acc = 0.f;
    for (int n = st; n < en; n++) acc += __half2float(g_h[(size_t)n * HID + t]);
    __shared__ float pooled[HID];
    float cnt = (float)(en - st);
    if (cnt < 1.f) cnt = 1.f;
    pooled[t] = acc / cnt;
    __syncthreads();
    if (t < OUTF) {
        float o = bout[t];
        #pragma unroll 8
        for (int k = 0; k < HID; k++) o += pooled[k] * Wout[k * OUTF + t];
        out[(size_t)gg * OUTF + t] = o;
    }
}

// ---------------- launcher ----------------
extern "C" void kernel_launch(void* const* d_in, const int* in_sizes, int n_in,
                              void* d_out, int out_size) {
    const float* x     = (const float*)d_in[0];
    const void*  ei    = d_in[1];
    const void*  batch = d_in[2];
    const float* W1 = (const float*)d_in[3];  const float* b1 = (const float*)d_in[4];
    const float* W2 = (const float*)d_in[5];  const float* b2 = (const float*)d_in[6];
    const float* W3 = (const float*)d_in[7];  const float* b3 = (const float*)d_in[8];
    const float* Wout = (const float*)d_in[9]; const float* bout = (const float*)d_in[10];
    float* out = (float*)d_out;

    int dev = 0;
    cudaGetDevice(&dev);
    int sms = 0;
    cudaDeviceGetAttribute(&sms, cudaDevAttrMultiProcessorCount, dev);
    int per = 0;
    cudaOccupancyMaxActiveBlocksPerMultiprocessor(&per, k_setup, 256, 0);
    if (per < 1) per = 1;
    if (sms < 1) sms = 1;
    int NB = sms * per;   // guaranteed co-resident -> grid barrier is live

    const int agg_blocks = (NN + 7) / 8;     // warp per node
    const int mma_blocks = (NN + 63) / 64;

    // K1: entire graph-structure setup in ONE persistent high-occupancy kernel
    k_setup<<<NB, 256>>>(x, ei, batch, W2, W3, NB);

    // K2: layer 1 (fused agg + gemm)
    k_aggx_gemm1<<<(NN + 63) / 64, 256>>>(W1, b1);
    // K3/K4: layer 2
    k_gemm_mma<<<mma_blocks, 256>>>(0);
    k_agg_h<<<agg_blocks, 256>>>(b2);
    // K5/K6: layer 3
    k_gemm_mma<<<mma_blocks, 256>>>(1);
    k_agg_h<<<agg_blocks, 256>>>(b3);
    // K7: pool + head
    k_pool<<<NG, HID>>>(Wout, bout, out);
}